// round 10
// baseline (speedup 1.0000x reference)
#include <cuda_runtime.h>

// Problem constants
#define B_   2
#define N_   4
#define BN_  8
#define C_   64
#define HF_  64
#define WF_  64
#define XV_  128
#define YV_  128
#define ZV_  8
#define HW_  (HF_ * WF_)          // 4096

#define ROWF4_  (C_ / 4)          // float4 per pixel: 16
#define LINEF4_ (WF_ * ROWF4_)    // float4 per image row: 1024

// Scratch (allocations forbidden -> __device__ globals)
__device__ float g_mats[BN_ * 12];          // P0,P1,P2 rows per camera
__device__ float g_featsT[BN_ * HW_ * C_];  // feats transposed to (bn, h, w, c)

// ---------------------------------------------------------------------------
// Kernel 1: transpose feats (bn, c, hw) -> (bn, hw, c), float4 both sides.
// Matrix precompute folded into block (0,0,0).
// ---------------------------------------------------------------------------
__global__ void __launch_bounds__(256) transpose_feats_kernel(
        const float* __restrict__ feats,
        const float* __restrict__ intrins,
        const float* __restrict__ extrins) {
    if (blockIdx.x == 0 && blockIdx.y == 0 && blockIdx.z == 0 && threadIdx.x < BN_) {
        int bn = threadIdx.x;
        const float* E = extrins + bn * 16;
        const float* K = intrins + bn * 16;
        float M[3][4];
#pragma unroll
        for (int i = 0; i < 3; i++) {
            float r0 = E[0 * 4 + i];
            float r1 = E[1 * 4 + i];
            float r2 = E[2 * 4 + i];
            M[i][0] = r0; M[i][1] = r1; M[i][2] = r2;
            M[i][3] = -(r0 * E[3] + r1 * E[7] + r2 * E[11]);
        }
        float fx = K[0] * 0.125f;
        float fy = K[5] * 0.125f;
        float x0 = K[2] * 0.125f;
        float y0 = K[6] * 0.125f;
        float* P = g_mats + bn * 12;
#pragma unroll
        for (int k = 0; k < 4; k++) {
            P[0 * 4 + k] = fx * M[0][k] + x0 * M[2][k];
            P[1 * 4 + k] = fy * M[1][k] + y0 * M[2][k];
            P[2 * 4 + k] = M[2][k];
        }
    }

    __shared__ float tile[32][33];
    int bn = blockIdx.z;
    int c0 = blockIdx.y * 32;
    int p0 = blockIdx.x * 32;
    int tx = threadIdx.x & 7;    // p-float4 index within tile
    int ty = threadIdx.x >> 3;   // c row 0..31

    const float4* in4 = (const float4*)(feats + (size_t)bn * C_ * HW_);
    float4 v = in4[(((c0 + ty) * HW_ + p0) >> 2) + tx];
    tile[ty][4 * tx + 0] = v.x;
    tile[ty][4 * tx + 1] = v.y;
    tile[ty][4 * tx + 2] = v.z;
    tile[ty][4 * tx + 3] = v.w;
    __syncthreads();

    float4 w;
    w.x = tile[4 * tx + 0][ty];
    w.y = tile[4 * tx + 1][ty];
    w.z = tile[4 * tx + 2][ty];
    w.w = tile[4 * tx + 3][ty];
    float4* out4 = (float4*)(g_featsT + (size_t)bn * HW_ * C_);
    out4[(((p0 + ty) * C_ + c0) >> 2) + tx] = w;
}

// ---------------------------------------------------------------------------
// Kernel 2: BRANCHLESS projection + bilinear gather + masked camera mean.
// One thread per (b, z, x, y) voxel, y fastest -> coalesced stores.
// No divergent regions in the hot loop: invalid (voxel,cam) pairs use
// offset 0 (all such lanes hit one cached line -> ~1 extra broadcast
// wavefront) and zero weights (0 * finite = 0, sums bit-identical).
// Straight-line code lets ptxas software-pipeline LDGs across cameras and
// chunks, hiding the 234-cyc L2 gather latency that the BSSY regions of
// previous rounds kept exposed. Per-element reduction is a 4-deep FFMA
// chain (acc folded in) = 4 ops/elem/cam.
// ---------------------------------------------------------------------------
__global__ void __launch_bounds__(128, 8) bev_unproject_kernel(float* __restrict__ out) {
    int t = blockIdx.x * 128 + threadIdx.x;
    int y = t & 127;
    int x = (t >> 7) & 127;
    int z = (t >> 14) & 7;
    int b = t >> 17;

    __shared__ float sm[BN_ * 12];
    if (threadIdx.x < BN_ * 12) sm[threadIdx.x] = g_mats[threadIdx.x];
    __syncthreads();

    // voxel center in cam0/ref coords
    float X = (float)x * 0.8f - 50.8f;
    float Y = (float)y * 0.8f - 50.8f;
    float Z = (float)z * 0.5f - 2.75f;

    const float4* __restrict__ F = (const float4*)g_featsT;
    const float4* p[4];          // per-camera corner00 base (F when invalid)
    float ax0[4], ax1[4], ay0[4], ay1[4];
    int cnt = 0;

#pragma unroll
    for (int n = 0; n < 4; n++) {
        const float* P = sm + (b * 4 + n) * 12;
        float xp = P[0] * X + P[1] * Y + P[2]  * Z + P[3];
        float yp = P[4] * X + P[5] * Y + P[6]  * Z + P[7];
        float zc = P[8] * X + P[9] * Y + P[10] * Z + P[11];

        float r  = 1.0f / fmaxf(zc, 1e-6f);
        float sx = xp * r;
        float sy = yp * r;

        bool valid = (sx > -0.5f) & (sx < 63.5f) & (sy > -0.5f) & (sy < 63.5f) & (zc > 0.0f);
        cnt += valid ? 1 : 0;

        // candidates (garbage when invalid; all selected away below)
        float px = sx - 0.5f, py = sy - 0.5f;
        float x0f = floorf(px), y0f = floorf(py);
        float wx = px - x0f,    wy = py - y0f;
        int xi = (int)x0f;      // valid => in [-1, 62]; +1 corner in-bounds
        int yi = (int)y0f;
        bool lv = (xi >= 0);
        bool tv = (yi >= 0);
        int xc = lv ? xi : 0;
        int yc = tv ? yi : 0;

        // branchless selects: invalid -> offset 0, all weights 0
        float cax0 = lv ? (1.0f - wx) : wx;
        float cax1 = lv ? wx : 0.0f;
        float cay0 = tv ? (1.0f - wy) : wy;
        float cay1 = tv ? wy : 0.0f;
        ax0[n] = valid ? cax0 : 0.0f;
        ax1[n] = valid ? cax1 : 0.0f;
        ay0[n] = valid ? cay0 : 0.0f;
        ay1[n] = valid ? cay1 : 0.0f;

        int bn = b * 4 + n;
        int offc = ((bn * HF_ + yc) * WF_ + xc) * ROWF4_;
        p[n] = F + (size_t)(valid ? offc : 0);
    }

    // fold 1/(eps + #valid) into the y-axis weights
    const float r1 = 1.0f / (1e-6f + 1.0f);
    const float r2 = 1.0f / (1e-6f + 2.0f);
    const float r3 = 1.0f / (1e-6f + 3.0f);
    const float r4 = 1.0f / (1e-6f + 4.0f);
    float rcp = (cnt <= 1) ? r1 : (cnt == 2) ? r2 : (cnt == 3) ? r3 : r4;

    float w00[4], w10[4], w01[4], w11[4];
#pragma unroll
    for (int n = 0; n < 4; n++) {
        float sy0 = ay0[n] * rcp, sy1 = ay1[n] * rcp;
        w00[n] = ax0[n] * sy0;
        w10[n] = ax1[n] * sy0;
        w01[n] = ax0[n] * sy1;
        w11[n] = ax1[n] * sy1;
    }

    // out[b, c*8+z, x, y]
    float* ob = out + ((b * C_) * ZV_ + z) * (XV_ * YV_) + x * YV_ + y;
    const int cstride = ZV_ * XV_ * YV_;   // 131072

#pragma unroll
    for (int ch = 0; ch < C_ / 8; ch++) {   // 8 channels = 2 float4 per corner
        float acc[8] = {0.f, 0.f, 0.f, 0.f, 0.f, 0.f, 0.f, 0.f};
#pragma unroll
        for (int n = 0; n < 4; n++) {
            const float4* q = p[n];         // straight-line, no branches
            float a = w00[n], bw = w10[n], c2 = w01[n], d = w11[n];
#pragma unroll
            for (int k = 0; k < 2; k++) {
                float4 g00 = __ldg(q + ch * 2 + k);
                float4 g10 = __ldg(q + ch * 2 + k + ROWF4_);             // +16
                float4 g01 = __ldg(q + ch * 2 + k + LINEF4_);            // +1024
                float4 g11 = __ldg(q + ch * 2 + k + LINEF4_ + ROWF4_);   // +1040
                acc[4*k+0] = fmaf(g00.x, a, fmaf(g10.x, bw, fmaf(g01.x, c2, fmaf(g11.x, d, acc[4*k+0]))));
                acc[4*k+1] = fmaf(g00.y, a, fmaf(g10.y, bw, fmaf(g01.y, c2, fmaf(g11.y, d, acc[4*k+1]))));
                acc[4*k+2] = fmaf(g00.z, a, fmaf(g10.z, bw, fmaf(g01.z, c2, fmaf(g11.z, d, acc[4*k+2]))));
                acc[4*k+3] = fmaf(g00.w, a, fmaf(g10.w, bw, fmaf(g01.w, c2, fmaf(g11.w, d, acc[4*k+3]))));
            }
        }
#pragma unroll
        for (int j = 0; j < 8; j++) {
            ob[(8 * ch + j) * cstride] = acc[j];
        }
    }
}

// ---------------------------------------------------------------------------
extern "C" void kernel_launch(void* const* d_in, const int* in_sizes, int n_in,
                              void* d_out, int out_size) {
    const float* feats   = (const float*)d_in[0];  // (2,4,64,64,64)
    const float* intrins = (const float*)d_in[1];  // (2,4,4,4)
    const float* extrins = (const float*)d_in[2];  // (2,4,4,4)
    float* out = (float*)d_out;                    // (2,512,128,128)

    dim3 tgrid(HW_ / 32, C_ / 32, BN_);
    transpose_feats_kernel<<<tgrid, 256>>>(feats, intrins, extrins);

    int total = B_ * ZV_ * XV_ * YV_;   // 262144 threads
    bev_unproject_kernel<<<total / 128, 128>>>(out);
}

// round 11
// speedup vs baseline: 1.2691x; 1.2691x over previous
#include <cuda_runtime.h>

// Problem constants
#define B_   2
#define N_   4
#define BN_  8
#define C_   64
#define HF_  64
#define WF_  64
#define XV_  128
#define YV_  128
#define ZV_  8
#define HW_  (HF_ * WF_)          // 4096

#define ROWF4_  (C_ / 4)          // float4 per pixel: 16
#define LINEF4_ (WF_ * ROWF4_)    // float4 per image row: 1024

// Scratch (allocations forbidden -> __device__ globals)
__device__ float g_mats[BN_ * 12];          // P0,P1,P2 rows per camera
__device__ float g_featsT[BN_ * HW_ * C_];  // feats transposed to (bn, h, w, c)

// ---------------------------------------------------------------------------
// Kernel 1: transpose feats (bn, c, hw) -> (bn, hw, c), float4 both sides.
// Matrix precompute folded into block (0,0,0).
// ---------------------------------------------------------------------------
__global__ void __launch_bounds__(256) transpose_feats_kernel(
        const float* __restrict__ feats,
        const float* __restrict__ intrins,
        const float* __restrict__ extrins) {
    if (blockIdx.x == 0 && blockIdx.y == 0 && blockIdx.z == 0 && threadIdx.x < BN_) {
        int bn = threadIdx.x;
        const float* E = extrins + bn * 16;
        const float* K = intrins + bn * 16;
        float M[3][4];
#pragma unroll
        for (int i = 0; i < 3; i++) {
            float r0 = E[0 * 4 + i];
            float r1 = E[1 * 4 + i];
            float r2 = E[2 * 4 + i];
            M[i][0] = r0; M[i][1] = r1; M[i][2] = r2;
            M[i][3] = -(r0 * E[3] + r1 * E[7] + r2 * E[11]);
        }
        float fx = K[0] * 0.125f;
        float fy = K[5] * 0.125f;
        float x0 = K[2] * 0.125f;
        float y0 = K[6] * 0.125f;
        float* P = g_mats + bn * 12;
#pragma unroll
        for (int k = 0; k < 4; k++) {
            P[0 * 4 + k] = fx * M[0][k] + x0 * M[2][k];
            P[1 * 4 + k] = fy * M[1][k] + y0 * M[2][k];
            P[2 * 4 + k] = M[2][k];
        }
    }

    __shared__ float tile[32][33];
    int bn = blockIdx.z;
    int c0 = blockIdx.y * 32;
    int p0 = blockIdx.x * 32;
    int tx = threadIdx.x & 7;    // p-float4 index within tile
    int ty = threadIdx.x >> 3;   // c row 0..31

    const float4* in4 = (const float4*)(feats + (size_t)bn * C_ * HW_);
    float4 v = in4[(((c0 + ty) * HW_ + p0) >> 2) + tx];
    tile[ty][4 * tx + 0] = v.x;
    tile[ty][4 * tx + 1] = v.y;
    tile[ty][4 * tx + 2] = v.z;
    tile[ty][4 * tx + 3] = v.w;
    __syncthreads();

    float4 w;
    w.x = tile[4 * tx + 0][ty];
    w.y = tile[4 * tx + 1][ty];
    w.z = tile[4 * tx + 2][ty];
    w.w = tile[4 * tx + 3][ty];
    float4* out4 = (float4*)(g_featsT + (size_t)bn * HW_ * C_);
    out4[(((p0 + ty) * C_ + c0) >> 2) + tx] = w;
}

// ---------------------------------------------------------------------------
// Kernel 2: R5 structure (best measured: guarded per-camera chunk-8 gathers,
// y-fastest coalesced stores) extended to TWO voxels per thread: (z, z+4).
//   * total warps 8192 -> 4096 = exactly ONE resident wave (no wave-2 tail)
//   * two independent gather streams per thread -> deeper MLP across the
//     divergent regions without enlarging any single region's register set
//   * acc stays 8 regs (voxel A's chunk is stored before voxel B's chunk)
//   * 32-bit gather offsets (not 64-bit pointers) to stay under 64 regs
// Per-voxel arithmetic and operation order identical to R5 -> same rel_err.
// ---------------------------------------------------------------------------
__global__ void __launch_bounds__(128, 8) bev_unproject_kernel(float* __restrict__ out) {
    int t = blockIdx.x * 128 + threadIdx.x;
    int y  = t & 127;
    int x  = (t >> 7) & 127;
    int z  = (t >> 14) & 3;   // voxel A: z ; voxel B: z+4
    int b  = t >> 16;

    __shared__ float sm[BN_ * 12];
    if (threadIdx.x < BN_ * 12) sm[threadIdx.x] = g_mats[threadIdx.x];
    __syncthreads();

    float X  = (float)x * 0.8f - 50.8f;
    float Y  = (float)y * 0.8f - 50.8f;
    float ZA = (float)z * 0.5f - 2.75f;   // ZB = ZA + 2.0f

    const float4* __restrict__ F = (const float4*)g_featsT;
    int   offA[4], offB[4];
    float wA00[4], wA10[4], wA01[4], wA11[4];
    float wB00[4], wB10[4], wB01[4], wB11[4];
    int maskA = 0, maskB = 0;

#pragma unroll
    for (int n = 0; n < 4; n++) {
        const float* P = sm + (b * 4 + n) * 12;
        int bn = b * 4 + n;
        int bnbase = bn * HF_ * WF_;

        float xpA = P[0] * X + P[1] * Y + P[2]  * ZA + P[3];
        float ypA = P[4] * X + P[5] * Y + P[6]  * ZA + P[7];
        float zcA = P[8] * X + P[9] * Y + P[10] * ZA + P[11];
        // voxel B: Z + 2.0 (4 voxels * 0.5m), projection is linear in Z
        float xpB = xpA + 2.0f * P[2];
        float ypB = ypA + 2.0f * P[6];
        float zcB = zcA + 2.0f * P[10];

        // ---- voxel A ----
        {
            float r  = 1.0f / fmaxf(zcA, 1e-6f);
            float sx = xpA * r;
            float sy = ypA * r;
            bool valid = (sx > -0.5f) & (sx < 63.5f) & (sy > -0.5f) & (sy < 63.5f) & (zcA > 0.0f);
            offA[n] = 0;
            wA00[n] = wA10[n] = wA01[n] = wA11[n] = 0.0f;
            if (valid) {
                float px = sx - 0.5f, py = sy - 0.5f;
                float x0f = floorf(px), y0f = floorf(py);
                float wx = px - x0f,    wy = py - y0f;
                int xi = (int)x0f, yi = (int)y0f;   // in [-1,62]; +1 in-bounds
                bool lv = (xi >= 0), tv = (yi >= 0);
                int xc = lv ? xi : 0, yc = tv ? yi : 0;
                float ax0 = lv ? (1.0f - wx) : wx;
                float ax1 = lv ? wx : 0.0f;
                float ay0 = tv ? (1.0f - wy) : wy;
                float ay1 = tv ? wy : 0.0f;
                wA00[n] = ax0 * ay0;  // rcp folded after mask known
                wA10[n] = ax1 * ay0;
                wA01[n] = ax0 * ay1;
                wA11[n] = ax1 * ay1;
                offA[n] = (bnbase + yc * WF_ + xc) * ROWF4_;
                maskA |= (1 << n);
            }
        }
        // ---- voxel B ----
        {
            float r  = 1.0f / fmaxf(zcB, 1e-6f);
            float sx = xpB * r;
            float sy = ypB * r;
            bool valid = (sx > -0.5f) & (sx < 63.5f) & (sy > -0.5f) & (sy < 63.5f) & (zcB > 0.0f);
            offB[n] = 0;
            wB00[n] = wB10[n] = wB01[n] = wB11[n] = 0.0f;
            if (valid) {
                float px = sx - 0.5f, py = sy - 0.5f;
                float x0f = floorf(px), y0f = floorf(py);
                float wx = px - x0f,    wy = py - y0f;
                int xi = (int)x0f, yi = (int)y0f;
                bool lv = (xi >= 0), tv = (yi >= 0);
                int xc = lv ? xi : 0, yc = tv ? yi : 0;
                float ax0 = lv ? (1.0f - wx) : wx;
                float ax1 = lv ? wx : 0.0f;
                float ay0 = tv ? (1.0f - wy) : wy;
                float ay1 = tv ? wy : 0.0f;
                wB00[n] = ax0 * ay0;
                wB10[n] = ax1 * ay0;
                wB01[n] = ax0 * ay1;
                wB11[n] = ax1 * ay1;
                offB[n] = (bnbase + yc * WF_ + xc) * ROWF4_;
                maskB |= (1 << n);
            }
        }
    }

    // fold 1/(eps + #valid) into the weights.
    // NOTE vs R5 rounding: R5 scaled the y-axis pair (ay*rcp) before the
    // w products; here we scale the final w products. Both are two-rounding
    // paths of the same exact value; difference <= 1 ulp, immaterial at 1e-3.
    const float rc1 = 1.0f / (1e-6f + 1.0f);
    const float rc2 = 1.0f / (1e-6f + 2.0f);
    const float rc3 = 1.0f / (1e-6f + 3.0f);
    const float rc4 = 1.0f / (1e-6f + 4.0f);
    int cA = __popc(maskA), cB = __popc(maskB);
    float rA = (cA <= 1) ? rc1 : (cA == 2) ? rc2 : (cA == 3) ? rc3 : rc4;
    float rB = (cB <= 1) ? rc1 : (cB == 2) ? rc2 : (cB == 3) ? rc3 : rc4;
#pragma unroll
    for (int n = 0; n < 4; n++) {
        wA00[n] *= rA; wA10[n] *= rA; wA01[n] *= rA; wA11[n] *= rA;
        wB00[n] *= rB; wB10[n] *= rB; wB01[n] *= rB; wB11[n] *= rB;
    }

    // out[b, c*8+z, x, y]
    float* obA = out + ((b * C_) * ZV_ + z) * (XV_ * YV_) + x * YV_ + y;
    float* obB = obA + 4 * (XV_ * YV_);
    const int cstride = ZV_ * XV_ * YV_;   // 131072

#pragma unroll
    for (int ch = 0; ch < C_ / 8; ch++) {   // 8 channels = 2 float4 per corner
        // ---- voxel A chunk ----
        {
            float acc[8] = {0.f, 0.f, 0.f, 0.f, 0.f, 0.f, 0.f, 0.f};
#pragma unroll
            for (int n = 0; n < 4; n++) {
                if (maskA & (1 << n)) {
                    const float4* q = F + offA[n] + ch * 2;
                    float a = wA00[n], bw = wA10[n], c2 = wA01[n], d = wA11[n];
#pragma unroll
                    for (int k = 0; k < 2; k++) {
                        float4 g00 = __ldg(q + k);
                        float4 g10 = __ldg(q + k + ROWF4_);
                        float4 g01 = __ldg(q + k + LINEF4_);
                        float4 g11 = __ldg(q + k + LINEF4_ + ROWF4_);
                        acc[4*k+0] += ((g00.x * a + g10.x * bw) + g01.x * c2) + g11.x * d;
                        acc[4*k+1] += ((g00.y * a + g10.y * bw) + g01.y * c2) + g11.y * d;
                        acc[4*k+2] += ((g00.z * a + g10.z * bw) + g01.z * c2) + g11.z * d;
                        acc[4*k+3] += ((g00.w * a + g10.w * bw) + g01.w * c2) + g11.w * d;
                    }
                }
            }
#pragma unroll
            for (int j = 0; j < 8; j++) obA[(8 * ch + j) * cstride] = acc[j];
        }
        // ---- voxel B chunk ----
        {
            float acc[8] = {0.f, 0.f, 0.f, 0.f, 0.f, 0.f, 0.f, 0.f};
#pragma unroll
            for (int n = 0; n < 4; n++) {
                if (maskB & (1 << n)) {
                    const float4* q = F + offB[n] + ch * 2;
                    float a = wB00[n], bw = wB10[n], c2 = wB01[n], d = wB11[n];
#pragma unroll
                    for (int k = 0; k < 2; k++) {
                        float4 g00 = __ldg(q + k);
                        float4 g10 = __ldg(q + k + ROWF4_);
                        float4 g01 = __ldg(q + k + LINEF4_);
                        float4 g11 = __ldg(q + k + LINEF4_ + ROWF4_);
                        acc[4*k+0] += ((g00.x * a + g10.x * bw) + g01.x * c2) + g11.x * d;
                        acc[4*k+1] += ((g00.y * a + g10.y * bw) + g01.y * c2) + g11.y * d;
                        acc[4*k+2] += ((g00.z * a + g10.z * bw) + g01.z * c2) + g11.z * d;
                        acc[4*k+3] += ((g00.w * a + g10.w * bw) + g01.w * c2) + g11.w * d;
                    }
                }
            }
#pragma unroll
            for (int j = 0; j < 8; j++) obB[(8 * ch + j) * cstride] = acc[j];
        }
    }
}

// ---------------------------------------------------------------------------
extern "C" void kernel_launch(void* const* d_in, const int* in_sizes, int n_in,
                              void* d_out, int out_size) {
    const float* feats   = (const float*)d_in[0];  // (2,4,64,64,64)
    const float* intrins = (const float*)d_in[1];  // (2,4,4,4)
    const float* extrins = (const float*)d_in[2];  // (2,4,4,4)
    float* out = (float*)d_out;                    // (2,512,128,128)

    dim3 tgrid(HW_ / 32, C_ / 32, BN_);
    transpose_feats_kernel<<<tgrid, 256>>>(feats, intrins, extrins);

    // 2 voxels per thread (z, z+4): 131072 threads -> 1024 blocks of 128
    int total = B_ * (ZV_ / 2) * XV_ * YV_;
    bev_unproject_kernel<<<total / 128, 128>>>(out);
}

// round 12
// speedup vs baseline: 1.4447x; 1.1383x over previous
#include <cuda_runtime.h>

// Problem constants
#define B_   2
#define N_   4
#define BN_  8
#define C_   64
#define HF_  64
#define WF_  64
#define XV_  128
#define YV_  128
#define ZV_  8
#define HW_  (HF_ * WF_)          // 4096

#define ROWF4_  (C_ / 4)          // float4 per pixel: 16
#define LINEF4_ (WF_ * ROWF4_)    // float4 per image row: 1024

// Scratch (allocations forbidden -> __device__ globals)
__device__ float g_mats[BN_ * 12];          // P0,P1,P2 rows per camera
__device__ float g_featsT[BN_ * HW_ * C_];  // feats transposed to (bn, h, w, c)

// ---------------------------------------------------------------------------
// Kernel 1: transpose feats (bn, c, hw) -> (bn, hw, c), float4 both sides.
// Matrix precompute folded into block (0,0,0).
// ---------------------------------------------------------------------------
__global__ void __launch_bounds__(256) transpose_feats_kernel(
        const float* __restrict__ feats,
        const float* __restrict__ intrins,
        const float* __restrict__ extrins) {
    if (blockIdx.x == 0 && blockIdx.y == 0 && blockIdx.z == 0 && threadIdx.x < BN_) {
        int bn = threadIdx.x;
        const float* E = extrins + bn * 16;
        const float* K = intrins + bn * 16;
        float M[3][4];
#pragma unroll
        for (int i = 0; i < 3; i++) {
            float r0 = E[0 * 4 + i];
            float r1 = E[1 * 4 + i];
            float r2 = E[2 * 4 + i];
            M[i][0] = r0; M[i][1] = r1; M[i][2] = r2;
            M[i][3] = -(r0 * E[3] + r1 * E[7] + r2 * E[11]);
        }
        float fx = K[0] * 0.125f;
        float fy = K[5] * 0.125f;
        float x0 = K[2] * 0.125f;
        float y0 = K[6] * 0.125f;
        float* P = g_mats + bn * 12;
#pragma unroll
        for (int k = 0; k < 4; k++) {
            P[0 * 4 + k] = fx * M[0][k] + x0 * M[2][k];
            P[1 * 4 + k] = fy * M[1][k] + y0 * M[2][k];
            P[2 * 4 + k] = M[2][k];
        }
    }

    __shared__ float tile[32][33];
    int bn = blockIdx.z;
    int c0 = blockIdx.y * 32;
    int p0 = blockIdx.x * 32;
    int tx = threadIdx.x & 7;    // p-float4 index within tile
    int ty = threadIdx.x >> 3;   // c row 0..31

    const float4* in4 = (const float4*)(feats + (size_t)bn * C_ * HW_);
    float4 v = in4[(((c0 + ty) * HW_ + p0) >> 2) + tx];
    tile[ty][4 * tx + 0] = v.x;
    tile[ty][4 * tx + 1] = v.y;
    tile[ty][4 * tx + 2] = v.z;
    tile[ty][4 * tx + 3] = v.w;
    __syncthreads();

    float4 w;
    w.x = tile[4 * tx + 0][ty];
    w.y = tile[4 * tx + 1][ty];
    w.z = tile[4 * tx + 2][ty];
    w.w = tile[4 * tx + 3][ty];
    float4* out4 = (float4*)(g_featsT + (size_t)bn * HW_ * C_);
    out4[(((p0 + ty) * C_ + c0) >> 2) + tx] = w;
}

// ---------------------------------------------------------------------------
// Kernel 2: main projection + bilinear gather + masked camera mean.
// THE R5 CHAMPION (27.68us measured), restored verbatim:
//   * one thread per (b, z, x, y) voxel, y fastest -> coalesced stores
//   * fixed-stride corners (+0, +16, +1024, +1040 float4) from one
//     per-camera base pointer; edge clamp via per-axis weight swap
//   * camera-mean reciprocal (popcount of valid mask) folded into weights
//   * guarded chunk-8 channel loop (2 float4/corner per divergent region)
//   * single reciprocal replaces the two per-camera divides
// Every structural variant tried in R6-R11 regressed; this is the measured
// optimum of the latency/issue/L1 trade surface at ~28 resident warps/SM.
// ---------------------------------------------------------------------------
__global__ void __launch_bounds__(128, 9) bev_unproject_kernel(float* __restrict__ out) {
    int t = blockIdx.x * 128 + threadIdx.x;
    int y = t & 127;
    int x = (t >> 7) & 127;
    int z = (t >> 14) & 7;
    int b = t >> 17;

    __shared__ float sm[BN_ * 12];
    if (threadIdx.x < BN_ * 12) sm[threadIdx.x] = g_mats[threadIdx.x];
    __syncthreads();

    // voxel center in cam0/ref coords
    float X = (float)x * 0.8f - 50.8f;
    float Y = (float)y * 0.8f - 50.8f;
    float Z = (float)z * 0.5f - 2.75f;

    const float4* __restrict__ F = (const float4*)g_featsT;
    const float4* p[4];          // per-camera corner00 base pointer
    float ax0[4], ax1[4], ay0[4], ay1[4];
    int mask = 0;

#pragma unroll
    for (int n = 0; n < 4; n++) {
        const float* P = sm + (b * 4 + n) * 12;
        float xp = P[0] * X + P[1] * Y + P[2]  * Z + P[3];
        float yp = P[4] * X + P[5] * Y + P[6]  * Z + P[7];
        float zc = P[8] * X + P[9] * Y + P[10] * Z + P[11];

        float r  = 1.0f / fmaxf(zc, 1e-6f);   // one exact div, two muls
        float sx = xp * r;
        float sy = yp * r;

        bool valid = (sx > -0.5f) & (sx < 63.5f) & (sy > -0.5f) & (sy < 63.5f) & (zc > 0.0f);

        p[n] = F;
        ax0[n] = ax1[n] = ay0[n] = ay1[n] = 0.0f;

        if (valid) {
            float px = sx - 0.5f, py = sy - 0.5f;
            float x0f = floorf(px), y0f = floorf(py);
            float wx = px - x0f,    wy = py - y0f;
            int xi = (int)x0f;      // in [-1, 62]; xi+1 always in-bounds
            int yi = (int)y0f;      // in [-1, 62]; yi+1 always in-bounds
            bool lv = (xi >= 0);
            bool tv = (yi >= 0);
            int xc = lv ? xi : 0;
            int yc = tv ? yi : 0;
            // per-axis weights with edge swap (bit-identical products)
            ax0[n] = lv ? (1.0f - wx) : wx;
            ax1[n] = lv ? wx : 0.0f;
            ay0[n] = tv ? (1.0f - wy) : wy;
            ay1[n] = tv ? wy : 0.0f;
            int bn = b * 4 + n;
            p[n] = F + (size_t)((bn * HF_ + yc) * WF_ + xc) * ROWF4_;
            mask |= (1 << n);
        }
    }

    // fold 1/(eps + #valid) into the y-axis weights
    int cnt = __popc(mask);
    const float r1 = 1.0f / (1e-6f + 1.0f);
    const float r2 = 1.0f / (1e-6f + 2.0f);
    const float r3 = 1.0f / (1e-6f + 3.0f);
    const float r4 = 1.0f / (1e-6f + 4.0f);
    float rcp = (cnt <= 1) ? r1 : (cnt == 2) ? r2 : (cnt == 3) ? r3 : r4;

    float w00[4], w10[4], w01[4], w11[4];
#pragma unroll
    for (int n = 0; n < 4; n++) {
        float sy0 = ay0[n] * rcp, sy1 = ay1[n] * rcp;
        w00[n] = ax0[n] * sy0;
        w10[n] = ax1[n] * sy0;
        w01[n] = ax0[n] * sy1;
        w11[n] = ax1[n] * sy1;
    }

    // out[b, c*8+z, x, y]
    float* ob = out + ((b * C_) * ZV_ + z) * (XV_ * YV_) + x * YV_ + y;
    const int cstride = ZV_ * XV_ * YV_;   // 131072

#pragma unroll
    for (int ch = 0; ch < C_ / 8; ch++) {   // 8 channels = 2 float4 per corner
        float acc[8] = {0.f, 0.f, 0.f, 0.f, 0.f, 0.f, 0.f, 0.f};
#pragma unroll
        for (int n = 0; n < 4; n++) {
            if (mask & (1 << n)) {
                const float4* q = p[n] + ch * 2;
                float a = w00[n], bw = w10[n], c2 = w01[n], d = w11[n];
#pragma unroll
                for (int k = 0; k < 2; k++) {
                    float4 g00 = __ldg(q + k);
                    float4 g10 = __ldg(q + k + ROWF4_);             // +16
                    float4 g01 = __ldg(q + k + LINEF4_);            // +1024
                    float4 g11 = __ldg(q + k + LINEF4_ + ROWF4_);   // +1040
                    acc[4 * k + 0] += ((g00.x * a + g10.x * bw) + g01.x * c2) + g11.x * d;
                    acc[4 * k + 1] += ((g00.y * a + g10.y * bw) + g01.y * c2) + g11.y * d;
                    acc[4 * k + 2] += ((g00.z * a + g10.z * bw) + g01.z * c2) + g11.z * d;
                    acc[4 * k + 3] += ((g00.w * a + g10.w * bw) + g01.w * c2) + g11.w * d;
                }
            }
        }
#pragma unroll
        for (int j = 0; j < 8; j++) {
            ob[(8 * ch + j) * cstride] = acc[j];
        }
    }
}

// ---------------------------------------------------------------------------
extern "C" void kernel_launch(void* const* d_in, const int* in_sizes, int n_in,
                              void* d_out, int out_size) {
    const float* feats   = (const float*)d_in[0];  // (2,4,64,64,64)
    const float* intrins = (const float*)d_in[1];  // (2,4,4,4)
    const float* extrins = (const float*)d_in[2];  // (2,4,4,4)
    float* out = (float*)d_out;                    // (2,512,128,128)

    dim3 tgrid(HW_ / 32, C_ / 32, BN_);
    transpose_feats_kernel<<<tgrid, 256>>>(feats, intrins, extrins);

    int total = B_ * ZV_ * XV_ * YV_;   // 262144 threads
    bev_unproject_kernel<<<total / 128, 128>>>(out);
}